// round 12
// baseline (speedup 1.0000x reference)
#include <cuda_runtime.h>
#include <cuda_fp16.h>
#include <cstdint>

#define N_NODES 100000
#define N_EDGES 1600000
#define HDIM 128
#define EDIM 32
#define KDIM 288                 // 128 + 128 + 32 = 9 * 32
#define NCHUNK 9
#define N_TILES ((N_NODES + 127) / 128)   // 782
#define NB 98

// ---------------- device scratch (allocation-free rule) ----------------
__device__ __half g_xh[N_NODES * HDIM];    // fp16 copy of x
__device__ __half g_SxH[N_NODES * HDIM];   // fp16 segment_sum(x[src], dst)
__device__ __half g_SeH[N_NODES * EDIM];   // fp16 segment_sum(edge_attr, dst)
__device__ __half g_Wt[HDIM * KDIM];       // fp16 Wt[j][k] = Wcat[k][j]
__device__ int    g_deg[N_NODES];
__device__ int    g_off[N_NODES];
__device__ int    g_bsum[NB];
__device__ int    g_ctr;                   // last-block counter (reset in prep)
__device__ int2   g_rec[N_EDGES];

// ---------------- helpers ----------------
__device__ __forceinline__ uint32_t smem_u32(const void* p) {
    uint32_t a;
    asm("{ .reg .u64 t; cvta.to.shared.u64 t, %1; cvt.u32.u64 %0, t; }"
        : "=r"(a) : "l"(p));
    return a;
}
__device__ __forceinline__ void ldsm_x4(uint32_t* r, uint32_t addr) {
    asm volatile("ldmatrix.sync.aligned.m8n8.x4.shared.b16 {%0,%1,%2,%3}, [%4];"
                 : "=r"(r[0]), "=r"(r[1]), "=r"(r[2]), "=r"(r[3]) : "r"(addr));
}
__device__ __forceinline__ void ldsm_x2(uint32_t* r, uint32_t addr) {
    asm volatile("ldmatrix.sync.aligned.m8n8.x2.shared.b16 {%0,%1}, [%2];"
                 : "=r"(r[0]), "=r"(r[1]) : "r"(addr));
}
__device__ __forceinline__ void mma16816h(float* d, const uint32_t* a,
                                          const uint32_t* b) {
    asm volatile(
        "mma.sync.aligned.m16n8k16.row.col.f32.f16.f16.f32 "
        "{%0,%1,%2,%3}, {%4,%5,%6,%7}, {%8,%9}, {%0,%1,%2,%3};"
        : "+f"(d[0]), "+f"(d[1]), "+f"(d[2]), "+f"(d[3])
        : "r"(a[0]), "r"(a[1]), "r"(a[2]), "r"(a[3]), "r"(b[0]), "r"(b[1]));
}
__device__ __forceinline__ uint32_t pkh2(float a, float b) {
    __half2 t = __floats2half2_rn(a, b);
    return *reinterpret_cast<uint32_t*>(&t);
}

// GEMM smem (bytes): double-buffered A/B chunk tiles, 128 rows x 80B pitch
#define SM_A0  0
#define SM_B0  10240
#define SM_A1  20480
#define SM_B1  30720
#define SM_BS  40960
#define SM_BM  41472
#define SMEM_TOTAL 41984

// ===========================================================================
// 0) prep: zero degree histogram + fp16 weight transpose + reset counter
// ===========================================================================
__global__ void prep_kernel(const float* __restrict__ Wself,
                            const float* __restrict__ Wmsg) {
    int tid = blockIdx.x * blockDim.x + threadIdx.x;
    if (tid == 0) g_ctr = 0;
    if (tid < N_NODES) g_deg[tid] = 0;
    if (tid < HDIM * KDIM) {
        int j = tid / KDIM, k = tid % KDIM;
        float v = (k < HDIM) ? Wself[k * HDIM + j] : Wmsg[(k - HDIM) * HDIM + j];
        g_Wt[tid] = __float2half(v);
    }
}

// ===========================================================================
// 1) hist + x->fp16 conversion
// ===========================================================================
__global__ void hist_kernel(const int* __restrict__ ei,
                            const float* __restrict__ x) {
    int tid = blockIdx.x * blockDim.x + threadIdx.x;
    if (tid < N_EDGES) atomicAdd(&g_deg[__ldg(&ei[N_EDGES + tid])], 1);
    const int total4 = N_NODES * HDIM / 4;
    const int stride = gridDim.x * blockDim.x;
    for (int i = tid; i < total4; i += stride) {
        float4 f = __ldcs(reinterpret_cast<const float4*>(x) + i);
        uint2 u;
        u.x = pkh2(f.x, f.y);
        u.y = pkh2(f.z, f.w);
        reinterpret_cast<uint2*>(g_xh)[i] = u;
    }
}

// ===========================================================================
// 2) single-kernel scan: block-local exclusive in g_off, block sums in
//    g_bsum; the LAST finishing block scans g_bsum in place.
// ===========================================================================
__device__ __forceinline__ int warp_incl_scan(int v, int lane) {
#pragma unroll
    for (int d = 1; d < 32; d <<= 1) {
        int t = __shfl_up_sync(0xffffffffu, v, d);
        if (lane >= d) v += t;
    }
    return v;
}
__global__ void scan_kernel() {
    __shared__ int wsum[32];
    __shared__ bool is_last;
    int i = blockIdx.x * 1024 + threadIdx.x;
    int lane = threadIdx.x & 31, w = threadIdx.x >> 5;
    int v = (i < N_NODES) ? g_deg[i] : 0;
    int inc = warp_incl_scan(v, lane);
    if (lane == 31) wsum[w] = inc;
    __syncthreads();
    if (w == 0) {
        int s = wsum[lane];
        int si = warp_incl_scan(s, lane);
        wsum[lane] = si - s;
    }
    __syncthreads();
    int excl = inc - v + wsum[w];
    if (i < N_NODES) g_off[i] = excl;
    if (threadIdx.x == 1023) g_bsum[blockIdx.x] = excl + v;

    // last-finishing block scans the 98 block sums
    __threadfence();
    __syncthreads();                  // ensure the g_bsum store has issued
    if (threadIdx.x == 0) {
        int t = atomicAdd(&g_ctr, 1);
        is_last = (t == NB - 1);
    }
    __syncthreads();
    if (!is_last) return;

    __shared__ int wsum2[4];
    int j = threadIdx.x;
    int l2 = j & 31, w2 = j >> 5;
    int bv = (j < NB) ? g_bsum[j] : 0;
    int binc = (j < 128) ? warp_incl_scan(bv, l2) : 0;
    if (j < 128 && l2 == 31) wsum2[w2] = binc;
    __syncthreads();
    if (j == 0) {
        int c = 0;
#pragma unroll
        for (int k = 0; k < 4; k++) { int t2 = wsum2[k]; wsum2[k] = c; c += t2; }
    }
    __syncthreads();
    if (j < NB) g_bsum[j] = binc - bv + wsum2[w2];   // exclusive block bases
}

// ===========================================================================
// 3) reorder
// ===========================================================================
__global__ void reorder_kernel(const int* __restrict__ ei) {
    int e = blockIdx.x * blockDim.x + threadIdx.x;
    if (e >= N_EDGES) return;
    int src = __ldcs(&ei[e]);
    int dst = __ldcs(&ei[N_EDGES + e]);
    int pos = atomicAdd(&g_off[dst], 1) + __ldg(&g_bsum[dst >> 10]);
    g_rec[pos] = make_int2(src, e);
}

// ===========================================================================
// 4) gather: one warp per dst node. 4-edge batches, 2 edges per x-row LDG
//    (uint4 x 16 lanes = one 256B fp16 row), 1 full-warp ea LDG per batch.
//    5 warp-LDGs per 4 edges.
// ===========================================================================
__device__ __forceinline__ void acc8(float* acc, uint4 xv) {
    __half2* h = reinterpret_cast<__half2*>(&xv);
#pragma unroll
    for (int j = 0; j < 4; j++) {
        float2 f = __half22float2(h[j]);
        acc[2 * j]     += f.x;
        acc[2 * j + 1] += f.y;
    }
}

__global__ void __launch_bounds__(256)
gather_kernel(const float* __restrict__ ea) {
    int gw   = (blockIdx.x * blockDim.x + threadIdx.x) >> 5;
    int lane = threadIdx.x & 31;
    int nw   = (gridDim.x * blockDim.x) >> 5;
    const int half16 = lane & 15;     // k-slot: 8 halves each
    const int grp    = lane >> 4;     // 0: even edge of pair, 1: odd
    const int q      = lane & 7;      // ea quarter (float4 index)

    for (int n = gw; n < N_NODES; n += nw) {
        int beg = (n == 0) ? 0
                : __ldg(&g_off[n - 1]) + __ldg(&g_bsum[(n - 1) >> 10]);
        int end = __ldg(&g_off[n]) + __ldg(&g_bsum[n >> 10]);

        float acc[8];
#pragma unroll
        for (int j = 0; j < 8; j++) acc[j] = 0.f;
        float4 ae = make_float4(0.f, 0.f, 0.f, 0.f);
        int i = beg;

        // tail-style single edge (also used for peel): 16-lane x load (grp0),
        // 8-lane ea load
        auto one_edge = [&](int idx) {
            int2 r = __ldg(&g_rec[idx]);
            if (grp == 0) {
                uint4 xv = __ldg(reinterpret_cast<const uint4*>(
                    g_xh + (size_t)r.x * HDIM + half16 * 8));
                acc8(acc, xv);
            }
            if (lane < 8) {
                float4 w0 = __ldcs(&reinterpret_cast<const float4*>(
                    ea + (size_t)r.y * EDIM)[lane]);
                ae.x += w0.x; ae.y += w0.y; ae.z += w0.z; ae.w += w0.w;
            }
        };

        if ((i & 1) && i < end) { one_edge(i); i++; }

        for (; i + 3 < end; i += 4) {
            uint4 p0 = __ldcs(reinterpret_cast<const uint4*>(&g_rec[i]));
            uint4 p1 = __ldcs(reinterpret_cast<const uint4*>(&g_rec[i + 2]));
            // x loads: each covers 2 edges (grp0 -> even, grp1 -> odd)
            int srcA = grp ? (int)p0.z : (int)p0.x;   // edges i / i+1
            int srcB = grp ? (int)p1.z : (int)p1.x;   // edges i+2 / i+3
            uint4 xa = __ldg(reinterpret_cast<const uint4*>(
                g_xh + (size_t)srcA * HDIM + half16 * 8));
            uint4 xb = __ldg(reinterpret_cast<const uint4*>(
                g_xh + (size_t)srcB * HDIM + half16 * 8));
            // ea: lane -> (edge-group lane>>3, quarter q)
            int eid = (lane & 16) ? ((lane & 8) ? (int)p1.w : (int)p1.y)
                                  : ((lane & 8) ? (int)p0.w : (int)p0.y);
            float4 w = __ldcs(reinterpret_cast<const float4*>(
                ea + (size_t)eid * EDIM + q * 4));

            acc8(acc, xa);
            acc8(acc, xb);
            ae.x += w.x; ae.y += w.y; ae.z += w.z; ae.w += w.w;
        }

        for (; i < end; i++) one_edge(i);

        // fold grp1 x-partials into lanes 0-15
#pragma unroll
        for (int j = 0; j < 8; j++)
            acc[j] += __shfl_xor_sync(0xffffffffu, acc[j], 16);
        // fold ea partials across the 4 edge-groups -> lanes 0..7
        ae.x += __shfl_xor_sync(0xffffffffu, ae.x, 16);
        ae.y += __shfl_xor_sync(0xffffffffu, ae.y, 16);
        ae.z += __shfl_xor_sync(0xffffffffu, ae.z, 16);
        ae.w += __shfl_xor_sync(0xffffffffu, ae.w, 16);
        ae.x += __shfl_xor_sync(0xffffffffu, ae.x, 8);
        ae.y += __shfl_xor_sync(0xffffffffu, ae.y, 8);
        ae.z += __shfl_xor_sync(0xffffffffu, ae.z, 8);
        ae.w += __shfl_xor_sync(0xffffffffu, ae.w, 8);

        if (lane < 16) {
            uint4 ox;
            ox.x = pkh2(acc[0], acc[1]);
            ox.y = pkh2(acc[2], acc[3]);
            ox.z = pkh2(acc[4], acc[5]);
            ox.w = pkh2(acc[6], acc[7]);
            *reinterpret_cast<uint4*>(
                g_SxH + (size_t)n * HDIM + half16 * 8) = ox;
        }
        if (lane < 8) {
            uint2 oe;
            oe.x = pkh2(ae.x, ae.y);
            oe.y = pkh2(ae.z, ae.w);
            reinterpret_cast<uint2*>(g_SeH + (size_t)n * EDIM)[lane] = oe;
        }
    }
}

// ===========================================================================
// 5) single-product fp16 mma GEMM, double-buffered
// ===========================================================================
__global__ void __launch_bounds__(256)
node_gemm_mma(const float* __restrict__ bself,
              const float* __restrict__ bmsg,
              float* __restrict__ out) {
    __shared__ __align__(16) unsigned char sm[SMEM_TOTAL];
    const uint32_t sbase = smem_u32(sm);

    const int tid = threadIdx.x;
    const int lane = tid & 31;
    const int wid = tid >> 5;
    const int warp_m = wid & 3;
    const int warp_n = wid >> 2;

    float* bs = reinterpret_cast<float*>(sm + SM_BS);
    float* bm = reinterpret_cast<float*>(sm + SM_BM);
    if (tid < HDIM) { bs[tid] = bself[tid]; bm[tid] = bmsg[tid]; }

    const int n0 = blockIdx.x * 128;

    uint4 av[2], bv[2];
    float acc[2][8][4];
#pragma unroll
    for (int a = 0; a < 2; a++)
#pragma unroll
        for (int b = 0; b < 8; b++)
#pragma unroll
            for (int c = 0; c < 4; c++) acc[a][b][c] = 0.f;

    auto stage = [&](int c) {
        const __half* asrc;
        int astr;
        if (c < 4)      { asrc = g_xh  + 32 * c;       astr = HDIM; }
        else if (c < 8) { asrc = g_SxH + 32 * (c - 4); astr = HDIM; }
        else            { asrc = g_SeH;                astr = EDIM; }
#pragma unroll
        for (int t = 0; t < 2; t++) {
            int idx = tid + t * 256;
            int row = idx >> 2, qq = idx & 3;
            int gn = n0 + row;
            av[t] = (gn < N_NODES)
                ? __ldg(reinterpret_cast<const uint4*>(
                      asrc + (size_t)gn * astr + qq * 8))
                : make_uint4(0u, 0u, 0u, 0u);
            bv[t] = __ldg(reinterpret_cast<const uint4*>(
                g_Wt + (size_t)row * KDIM + c * 32 + qq * 8));
        }
    };
    auto commit = [&](int buf) {
        unsigned char* pa = sm + (buf ? SM_A1 : SM_A0);
        unsigned char* pb = sm + (buf ? SM_B1 : SM_B0);
#pragma unroll
        for (int t = 0; t < 2; t++) {
            int idx = tid + t * 256;
            int row = idx >> 2, qq = idx & 3;
            *reinterpret_cast<uint4*>(pa + row * 80 + qq * 16) = av[t];
            *reinterpret_cast<uint4*>(pb + row * 80 + qq * 16) = bv[t];
        }
    };

    const uint32_t a_row_off = (warp_m * 32 + (lane & 15)) * 80 + (lane >> 4) * 16;
    const uint32_t b_row_off = (warp_n * 64 + (lane & 7)) * 80 + ((lane >> 3) & 1) * 16;

    stage(0);
    commit(0);
    __syncthreads();

    for (int c = 0; c < NCHUNK; c++) {
        if (c + 1 < NCHUNK) stage(c + 1);

        const uint32_t sa = sbase + ((c & 1) ? SM_A1 : SM_A0);
        const uint32_t sb = sbase + ((c & 1) ? SM_B1 : SM_B0);
#pragma unroll
        for (int ks = 0; ks < 2; ks++) {
            uint32_t ah[2][4];
#pragma unroll
            for (int mf = 0; mf < 2; mf++)
                ldsm_x4(ah[mf], sa + a_row_off + mf * 16 * 80 + ks * 32);
#pragma unroll
            for (int nf = 0; nf < 8; nf++) {
                uint32_t bh[2];
                ldsm_x2(bh, sb + b_row_off + nf * 8 * 80 + ks * 32);
                mma16816h(acc[0][nf], ah[0], bh);
                mma16816h(acc[1][nf], ah[1], bh);
            }
        }
        if (c + 1 < NCHUNK) {
            commit((c + 1) & 1);
            __syncthreads();
        }
    }

    const int gid = lane >> 2, tig = lane & 3;
#pragma unroll
    for (int mf = 0; mf < 2; mf++) {
#pragma unroll
        for (int rr = 0; rr < 2; rr++) {
            int row = warp_m * 32 + mf * 16 + rr * 8 + gid;
            int gn = n0 + row;
            if (gn >= N_NODES) continue;
            float degf = (float)g_deg[gn];
#pragma unroll
            for (int nf = 0; nf < 8; nf++) {
                int j = warp_n * 64 + nf * 8 + tig * 2;
                float2 o;
                o.x = fmaxf(acc[mf][nf][rr * 2 + 0] + bs[j]     + degf * bm[j],     0.f);
                o.y = fmaxf(acc[mf][nf][rr * 2 + 1] + bs[j + 1] + degf * bm[j + 1], 0.f);
                *reinterpret_cast<float2*>(out + (size_t)gn * HDIM + j) = o;
            }
        }
    }
}

// ---------------------------------------------------------------------------
extern "C" void kernel_launch(void* const* d_in, const int* in_sizes, int n_in,
                              void* d_out, int out_size) {
    const float* x     = (const float*)d_in[0];
    const int*   ei    = (const int*)  d_in[1];
    const float* ea    = (const float*)d_in[2];
    const float* Wself = (const float*)d_in[3];
    const float* bself = (const float*)d_in[4];
    const float* Wmsg  = (const float*)d_in[5];
    const float* bmsg  = (const float*)d_in[6];
    float* out = (float*)d_out;

    prep_kernel<<<(N_NODES + 255) / 256, 256>>>(Wself, Wmsg);       // 0
    hist_kernel<<<(N_EDGES + 511) / 512, 512>>>(ei, x);             // 1
    scan_kernel<<<NB, 1024>>>();                                    // 2
    reorder_kernel<<<(N_EDGES + 511) / 512, 512>>>(ei);             // 3
    gather_kernel<<<148 * 12, 256>>>(ea);                           // 4
    node_gemm_mma<<<N_TILES, 256>>>(bself, bmsg, out);              // 5
}

// round 13
// speedup vs baseline: 1.0365x; 1.0365x over previous
#include <cuda_runtime.h>
#include <cuda_fp16.h>
#include <cstdint>

#define N_NODES 100000
#define N_EDGES 1600000
#define HDIM 128
#define EDIM 32
#define KDIM 288                 // 128 + 128 + 32 = 9 * 32
#define NCHUNK 9
#define N_TILES ((N_NODES + 127) / 128)   // 782
#define NB 98

// ---------------- device scratch (allocation-free rule) ----------------
// NOTE: g_deg is zero at module load and re-zeroed by node_gemm_mma's
// epilogue on every execution, so hist can atomically accumulate into it
// without a separate zeroing pass. g_ctr self-resets in scan_kernel.
__device__ __half g_xh[N_NODES * HDIM];    // fp16 copy of x
__device__ __half g_SxH[N_NODES * HDIM];   // fp16 segment_sum(x[src], dst)
__device__ __half g_SeH[N_NODES * EDIM];   // fp16 segment_sum(edge_attr, dst)
__device__ __half g_Wt[HDIM * KDIM];       // fp16 Wt[j][k] = Wcat[k][j]
__device__ int    g_deg[N_NODES];
__device__ int    g_off[N_NODES];
__device__ int    g_bsum[NB];
__device__ int    g_ctr;
__device__ int2   g_rec[N_EDGES];

// ---------------- helpers ----------------
__device__ __forceinline__ uint32_t smem_u32(const void* p) {
    uint32_t a;
    asm("{ .reg .u64 t; cvta.to.shared.u64 t, %1; cvt.u32.u64 %0, t; }"
        : "=r"(a) : "l"(p));
    return a;
}
__device__ __forceinline__ void ldsm_x4(uint32_t* r, uint32_t addr) {
    asm volatile("ldmatrix.sync.aligned.m8n8.x4.shared.b16 {%0,%1,%2,%3}, [%4];"
                 : "=r"(r[0]), "=r"(r[1]), "=r"(r[2]), "=r"(r[3]) : "r"(addr));
}
__device__ __forceinline__ void ldsm_x2(uint32_t* r, uint32_t addr) {
    asm volatile("ldmatrix.sync.aligned.m8n8.x2.shared.b16 {%0,%1}, [%2];"
                 : "=r"(r[0]), "=r"(r[1]) : "r"(addr));
}
__device__ __forceinline__ void mma16816h(float* d, const uint32_t* a,
                                          const uint32_t* b) {
    asm volatile(
        "mma.sync.aligned.m16n8k16.row.col.f32.f16.f16.f32 "
        "{%0,%1,%2,%3}, {%4,%5,%6,%7}, {%8,%9}, {%0,%1,%2,%3};"
        : "+f"(d[0]), "+f"(d[1]), "+f"(d[2]), "+f"(d[3])
        : "r"(a[0]), "r"(a[1]), "r"(a[2]), "r"(a[3]), "r"(b[0]), "r"(b[1]));
}
__device__ __forceinline__ uint32_t pkh2(float a, float b) {
    __half2 t = __floats2half2_rn(a, b);
    return *reinterpret_cast<uint32_t*>(&t);
}

// GEMM smem (bytes): double-buffered A/B chunk tiles, 128 rows x 80B pitch
#define SM_A0  0
#define SM_B0  10240
#define SM_A1  20480
#define SM_B1  30720
#define SM_BS  40960
#define SM_BM  41472
#define SMEM_TOTAL 41984

// ===========================================================================
// 0) hist: degree histogram + x->fp16 conversion + fp16 weight transpose
// ===========================================================================
__global__ void hist_kernel(const int* __restrict__ ei,
                            const float* __restrict__ x,
                            const float* __restrict__ Wself,
                            const float* __restrict__ Wmsg) {
    int tid = blockIdx.x * blockDim.x + threadIdx.x;
    if (tid < N_EDGES) atomicAdd(&g_deg[__ldg(&ei[N_EDGES + tid])], 1);
    if (tid < HDIM * KDIM) {
        int j = tid / KDIM, k = tid % KDIM;
        float v = (k < HDIM) ? Wself[k * HDIM + j] : Wmsg[(k - HDIM) * HDIM + j];
        g_Wt[tid] = __float2half(v);
    }
    const int total4 = N_NODES * HDIM / 4;
    const int stride = gridDim.x * blockDim.x;
    for (int i = tid; i < total4; i += stride) {
        float4 f = __ldcs(reinterpret_cast<const float4*>(x) + i);
        uint2 u;
        u.x = pkh2(f.x, f.y);
        u.y = pkh2(f.z, f.w);
        reinterpret_cast<uint2*>(g_xh)[i] = u;
    }
}

// ===========================================================================
// 1) single-kernel scan; last finishing block scans g_bsum and resets g_ctr
// ===========================================================================
__device__ __forceinline__ int warp_incl_scan(int v, int lane) {
#pragma unroll
    for (int d = 1; d < 32; d <<= 1) {
        int t = __shfl_up_sync(0xffffffffu, v, d);
        if (lane >= d) v += t;
    }
    return v;
}
__global__ void scan_kernel() {
    __shared__ int wsum[32];
    __shared__ bool is_last;
    int i = blockIdx.x * 1024 + threadIdx.x;
    int lane = threadIdx.x & 31, w = threadIdx.x >> 5;
    int v = (i < N_NODES) ? g_deg[i] : 0;
    int inc = warp_incl_scan(v, lane);
    if (lane == 31) wsum[w] = inc;
    __syncthreads();
    if (w == 0) {
        int s = wsum[lane];
        int si = warp_incl_scan(s, lane);
        wsum[lane] = si - s;
    }
    __syncthreads();
    int excl = inc - v + wsum[w];
    if (i < N_NODES) g_off[i] = excl;
    if (threadIdx.x == 1023) g_bsum[blockIdx.x] = excl + v;

    __threadfence();
    __syncthreads();
    if (threadIdx.x == 0) {
        int t = atomicAdd(&g_ctr, 1);
        is_last = (t == NB - 1);
    }
    __syncthreads();
    if (!is_last) return;

    __shared__ int wsum2[4];
    int j = threadIdx.x;
    int l2 = j & 31, w2 = j >> 5;
    int bv = (j < NB) ? g_bsum[j] : 0;
    int binc = (j < 128) ? warp_incl_scan(bv, l2) : 0;
    if (j < 128 && l2 == 31) wsum2[w2] = binc;
    __syncthreads();
    if (j == 0) {
        int c = 0;
#pragma unroll
        for (int k = 0; k < 4; k++) { int t2 = wsum2[k]; wsum2[k] = c; c += t2; }
    }
    __syncthreads();
    if (j < NB) g_bsum[j] = binc - bv + wsum2[w2];
    if (j == 0) g_ctr = 0;               // self-reset for next execution
}

// ===========================================================================
// 2) reorder
// ===========================================================================
__global__ void reorder_kernel(const int* __restrict__ ei) {
    int e = blockIdx.x * blockDim.x + threadIdx.x;
    if (e >= N_EDGES) return;
    int src = __ldcs(&ei[e]);
    int dst = __ldcs(&ei[N_EDGES + e]);
    int pos = atomicAdd(&g_off[dst], 1) + __ldg(&g_bsum[dst >> 10]);
    g_rec[pos] = make_int2(src, e);
}

// ===========================================================================
// 3) gather (R11-proven): one warp per dst node, 4-edge batches with
//    2 uniform uint4 rec loads + 4 full-warp x loads + 1 full-warp ea load.
// ===========================================================================
__device__ __forceinline__ float4 ld_xh(int src, int lane) {
    uint2 u = __ldg(reinterpret_cast<const uint2*>(
        g_xh + (size_t)src * HDIM + lane * 4));
    float2 a = __half22float2(*reinterpret_cast<__half2*>(&u.x));
    float2 b = __half22float2(*reinterpret_cast<__half2*>(&u.y));
    return make_float4(a.x, a.y, b.x, b.y);
}

__global__ void __launch_bounds__(256)
gather_kernel(const float* __restrict__ ea) {
    int gw   = (blockIdx.x * blockDim.x + threadIdx.x) >> 5;
    int lane = threadIdx.x & 31;
    int nw   = (gridDim.x * blockDim.x) >> 5;
    const int q = lane & 7;              // ea quarter (float4 index)

    for (int n = gw; n < N_NODES; n += nw) {
        int beg = (n == 0) ? 0
                : __ldg(&g_off[n - 1]) + __ldg(&g_bsum[(n - 1) >> 10]);
        int end = __ldg(&g_off[n]) + __ldg(&g_bsum[n >> 10]);

        float4 ax = make_float4(0.f, 0.f, 0.f, 0.f);
        float4 ae = make_float4(0.f, 0.f, 0.f, 0.f);
        int i = beg;

        if ((i & 1) && i < end) {
            int2 r0 = __ldg(&g_rec[i]);
            float4 v0 = ld_xh(r0.x, lane);
            ax.x += v0.x; ax.y += v0.y; ax.z += v0.z; ax.w += v0.w;
            if (lane < 8) {
                float4 w0 = __ldcs(&reinterpret_cast<const float4*>(
                    ea + (size_t)r0.y * EDIM)[lane]);
                ae.x += w0.x; ae.y += w0.y; ae.z += w0.z; ae.w += w0.w;
            }
            i++;
        }

        for (; i + 3 < end; i += 4) {
            uint4 p0 = __ldcs(reinterpret_cast<const uint4*>(&g_rec[i]));
            uint4 p1 = __ldcs(reinterpret_cast<const uint4*>(&g_rec[i + 2]));
            int s0 = (int)p0.x, e0 = (int)p0.y;
            int s1 = (int)p0.z, e1 = (int)p0.w;
            int s2 = (int)p1.x, e2 = (int)p1.y;
            int s3 = (int)p1.z, e3 = (int)p1.w;

            float4 v0 = ld_xh(s0, lane);
            float4 v1 = ld_xh(s1, lane);
            float4 v2 = ld_xh(s2, lane);
            float4 v3 = ld_xh(s3, lane);

            int eid = (lane & 16) ? ((lane & 8) ? e3 : e2)
                                  : ((lane & 8) ? e1 : e0);
            float4 w = __ldcs(reinterpret_cast<const float4*>(
                ea + (size_t)eid * EDIM + q * 4));

            ax.x += (v0.x + v1.x) + (v2.x + v3.x);
            ax.y += (v0.y + v1.y) + (v2.y + v3.y);
            ax.z += (v0.z + v1.z) + (v2.z + v3.z);
            ax.w += (v0.w + v1.w) + (v2.w + v3.w);
            ae.x += w.x; ae.y += w.y; ae.z += w.z; ae.w += w.w;
        }

        for (; i < end; i++) {
            int2 r0 = __ldg(&g_rec[i]);
            float4 v0 = ld_xh(r0.x, lane);
            ax.x += v0.x; ax.y += v0.y; ax.z += v0.z; ax.w += v0.w;
            if (lane < 8) {
                float4 w0 = __ldcs(&reinterpret_cast<const float4*>(
                    ea + (size_t)r0.y * EDIM)[lane]);
                ae.x += w0.x; ae.y += w0.y; ae.z += w0.z; ae.w += w0.w;
            }
        }

        ae.x += __shfl_xor_sync(0xffffffffu, ae.x, 16);
        ae.y += __shfl_xor_sync(0xffffffffu, ae.y, 16);
        ae.z += __shfl_xor_sync(0xffffffffu, ae.z, 16);
        ae.w += __shfl_xor_sync(0xffffffffu, ae.w, 16);
        ae.x += __shfl_xor_sync(0xffffffffu, ae.x, 8);
        ae.y += __shfl_xor_sync(0xffffffffu, ae.y, 8);
        ae.z += __shfl_xor_sync(0xffffffffu, ae.z, 8);
        ae.w += __shfl_xor_sync(0xffffffffu, ae.w, 8);

        uint2 ox;
        ox.x = pkh2(ax.x, ax.y);
        ox.y = pkh2(ax.z, ax.w);
        reinterpret_cast<uint2*>(g_SxH + (size_t)n * HDIM)[lane] = ox;
        if (lane < 8) {
            uint2 oe;
            oe.x = pkh2(ae.x, ae.y);
            oe.y = pkh2(ae.z, ae.w);
            reinterpret_cast<uint2*>(g_SeH + (size_t)n * EDIM)[lane] = oe;
        }
    }
}

// ===========================================================================
// 4) single-product fp16 mma GEMM, double-buffered.
//    Epilogue re-zeros g_deg for the NEXT execution (after all reads).
// ===========================================================================
__global__ void __launch_bounds__(256)
node_gemm_mma(const float* __restrict__ bself,
              const float* __restrict__ bmsg,
              float* __restrict__ out) {
    __shared__ __align__(16) unsigned char sm[SMEM_TOTAL];
    const uint32_t sbase = smem_u32(sm);

    const int tid = threadIdx.x;
    const int lane = tid & 31;
    const int wid = tid >> 5;
    const int warp_m = wid & 3;
    const int warp_n = wid >> 2;

    float* bs = reinterpret_cast<float*>(sm + SM_BS);
    float* bm = reinterpret_cast<float*>(sm + SM_BM);
    if (tid < HDIM) { bs[tid] = bself[tid]; bm[tid] = bmsg[tid]; }

    const int n0 = blockIdx.x * 128;

    uint4 av[2], bv[2];
    float acc[2][8][4];
#pragma unroll
    for (int a = 0; a < 2; a++)
#pragma unroll
        for (int b = 0; b < 8; b++)
#pragma unroll
            for (int c = 0; c < 4; c++) acc[a][b][c] = 0.f;

    auto stage = [&](int c) {
        const __half* asrc;
        int astr;
        if (c < 4)      { asrc = g_xh  + 32 * c;       astr = HDIM; }
        else if (c < 8) { asrc = g_SxH + 32 * (c - 4); astr = HDIM; }
        else            { asrc = g_SeH;                astr = EDIM; }
#pragma unroll
        for (int t = 0; t < 2; t++) {
            int idx = tid + t * 256;
            int row = idx >> 2, qq = idx & 3;
            int gn = n0 + row;
            av[t] = (gn < N_NODES)
                ? __ldg(reinterpret_cast<const uint4*>(
                      asrc + (size_t)gn * astr + qq * 8))
                : make_uint4(0u, 0u, 0u, 0u);
            bv[t] = __ldg(reinterpret_cast<const uint4*>(
                g_Wt + (size_t)row * KDIM + c * 32 + qq * 8));
        }
    };
    auto commit = [&](int buf) {
        unsigned char* pa = sm + (buf ? SM_A1 : SM_A0);
        unsigned char* pb = sm + (buf ? SM_B1 : SM_B0);
#pragma unroll
        for (int t = 0; t < 2; t++) {
            int idx = tid + t * 256;
            int row = idx >> 2, qq = idx & 3;
            *reinterpret_cast<uint4*>(pa + row * 80 + qq * 16) = av[t];
            *reinterpret_cast<uint4*>(pb + row * 80 + qq * 16) = bv[t];
        }
    };

    const uint32_t a_row_off = (warp_m * 32 + (lane & 15)) * 80 + (lane >> 4) * 16;
    const uint32_t b_row_off = (warp_n * 64 + (lane & 7)) * 80 + ((lane >> 3) & 1) * 16;

    stage(0);
    commit(0);
    __syncthreads();

    for (int c = 0; c < NCHUNK; c++) {
        if (c + 1 < NCHUNK) stage(c + 1);

        const uint32_t sa = sbase + ((c & 1) ? SM_A1 : SM_A0);
        const uint32_t sb = sbase + ((c & 1) ? SM_B1 : SM_B0);
#pragma unroll
        for (int ks = 0; ks < 2; ks++) {
            uint32_t ah[2][4];
#pragma unroll
            for (int mf = 0; mf < 2; mf++)
                ldsm_x4(ah[mf], sa + a_row_off + mf * 16 * 80 + ks * 32);
#pragma unroll
            for (int nf = 0; nf < 8; nf++) {
                uint32_t bh[2];
                ldsm_x2(bh, sb + b_row_off + nf * 8 * 80 + ks * 32);
                mma16816h(acc[0][nf], ah[0], bh);
                mma16816h(acc[1][nf], ah[1], bh);
            }
        }
        if (c + 1 < NCHUNK) {
            commit((c + 1) & 1);
            __syncthreads();
        }
    }

    const int gid = lane >> 2, tig = lane & 3;
#pragma unroll
    for (int mf = 0; mf < 2; mf++) {
#pragma unroll
        for (int rr = 0; rr < 2; rr++) {
            int row = warp_m * 32 + mf * 16 + rr * 8 + gid;
            int gn = n0 + row;
            if (gn >= N_NODES) continue;
            float degf = (float)g_deg[gn];
#pragma unroll
            for (int nf = 0; nf < 8; nf++) {
                int j = warp_n * 64 + nf * 8 + tig * 2;
                float2 o;
                o.x = fmaxf(acc[mf][nf][rr * 2 + 0] + bs[j]     + degf * bm[j],     0.f);
                o.y = fmaxf(acc[mf][nf][rr * 2 + 1] + bs[j + 1] + degf * bm[j + 1], 0.f);
                *reinterpret_cast<float2*>(out + (size_t)gn * HDIM + j) = o;
            }
        }
    }

    // all degf reads done -> re-zero this tile's degrees for next execution
    __syncthreads();
    if (tid < 128) {
        int gn = n0 + tid;
        if (gn < N_NODES) g_deg[gn] = 0;
    }
}

// ---------------------------------------------------------------------------
extern "C" void kernel_launch(void* const* d_in, const int* in_sizes, int n_in,
                              void* d_out, int out_size) {
    const float* x     = (const float*)d_in[0];
    const int*   ei    = (const int*)  d_in[1];
    const float* ea    = (const float*)d_in[2];
    const float* Wself = (const float*)d_in[3];
    const float* bself = (const float*)d_in[4];
    const float* Wmsg  = (const float*)d_in[5];
    const float* bmsg  = (const float*)d_in[6];
    float* out = (float*)d_out;

    hist_kernel<<<(N_EDGES + 511) / 512, 512>>>(ei, x, Wself, Wmsg); // 0
    scan_kernel<<<NB, 1024>>>();                                     // 1
    reorder_kernel<<<(N_EDGES + 511) / 512, 512>>>(ei);              // 2
    gather_kernel<<<148 * 12, 256>>>(ea);                            // 3 (profiled)
    node_gemm_mma<<<N_TILES, 256>>>(bself, bmsg, out);               // 4
}